// round 1
// baseline (speedup 1.0000x reference)
#include <cuda_runtime.h>
#include <math.h>

#define B_ 8
#define C_ 256
#define H_ 128
#define W_ 128
#define HW_ 16384
#define HEADS_ 8
#define HD_ 32

// ---------------- scratch (device globals; no allocation allowed) ------------
__device__ float g_bufA[B_ * C_ * HW_];          // q_pre, later t1 (gelu(dw(v,pe1)))
__device__ float g_bufB[B_ * 2 * C_ * HW_];      // kv_pre, later (first half) p_emb + hx
__device__ float g_q[B_ * C_ * HW_];
__device__ float g_k[B_ * C_ * HW_];
__device__ float g_v[B_ * C_ * HW_];
__device__ float g_Wq[C_ * C_];                  // q_w * ln1_w (folded)
__device__ float g_Wkv[2 * C_ * C_];             // kv_w * ln2_w (folded)
__device__ float g_bq[C_];
__device__ float g_bkv[2 * C_];
__device__ float g_rsq[C_];                      // row sums of folded weights
__device__ float g_rskv[2 * C_];
__device__ float g_mu[2 * B_ * HW_];             // LN stats: [tensor(x/hx)][b][p]
__device__ float g_rstd[2 * B_ * HW_];
__device__ float g_scale[2 * B_ * C_];           // 1/max(||row||,eps) for q (z=0), k (z=1)
__device__ float g_part[B_ * HEADS_ * 16 * 32 * 32];  // split-K gram partials
__device__ float g_attn[B_ * HEADS_ * 32 * 32];
__device__ float g_M[B_ * C_ * C_];              // ao_w @ blockdiag(attn) per batch

__device__ __forceinline__ float* buf_sel(int id) {
    switch (id) {
        case 0: return g_bufA;
        case 1: return g_bufB;
        case 2: return g_q;
        case 3: return g_k;
        case 4: return g_v;
    }
    return g_bufA;
}

// ---------------- weight prep: fold LN gamma/beta into conv1x1 ---------------
__global__ void prep_w_kernel(const float* __restrict__ qw, const float* __restrict__ qb,
                              const float* __restrict__ ln1w, const float* __restrict__ ln1b,
                              const float* __restrict__ kvw, const float* __restrict__ kvb,
                              const float* __restrict__ ln2w, const float* __restrict__ ln2b) {
    int r = blockIdx.x;
    int tid = threadIdx.x;  // 256 threads = one per input channel
    const float *w, *lnw, *lnb;
    float cb;
    float *dW, *dB, *dR;
    if (r < C_) {
        int o = r;
        w = qw + (size_t)o * C_; lnw = ln1w; lnb = ln1b; cb = qb[o];
        dW = g_Wq + (size_t)o * C_; dB = g_bq + o; dR = g_rsq + o;
    } else {
        int o = r - C_;
        w = kvw + (size_t)o * C_; lnw = ln2w; lnb = ln2b; cb = kvb[o];
        dW = g_Wkv + (size_t)o * C_; dB = g_bkv + o; dR = g_rskv + o;
    }
    float wv = w[tid];
    float we = wv * lnw[tid];
    dW[tid] = we;
    __shared__ float sh1[256], sh2[256];
    sh1[tid] = we;
    sh2[tid] = wv * lnb[tid];
    __syncthreads();
    for (int s = 128; s > 0; s >>= 1) {
        if (tid < s) { sh1[tid] += sh1[tid + s]; sh2[tid] += sh2[tid + s]; }
        __syncthreads();
    }
    if (tid == 0) { *dR = sh1[0]; *dB = cb + sh2[0]; }
}

// ---------------- per-pixel LN stats over channels ---------------------------
__global__ void ln_stats_kernel(const float* __restrict__ x, const float* __restrict__ hx) {
    int t = blockIdx.z, b = blockIdx.y;
    int p = blockIdx.x * 256 + threadIdx.x;
    const float* X = (t == 0 ? x : hx) + (size_t)b * C_ * HW_ + p;
    float s = 0.f, s2 = 0.f;
#pragma unroll 4
    for (int c = 0; c < C_; c++) {
        float v = X[(size_t)c * HW_];
        s += v; s2 += v * v;
    }
    float mu = s * (1.f / C_);
    float var = s2 * (1.f / C_) - mu * mu;
    int idx = (t * B_ + b) * HW_ + p;
    g_mu[idx] = mu;
    g_rstd[idx] = rsqrtf(var + 1e-5f);
}

// ---------------- batched GEMM with LN-fold epilogue -------------------------
// Y[b,o,p] = rstd[b,p] * (sum_c W[o,c]*X[b,c,p] - mu[b,p]*rowsum[o]) + bias[o]
__global__ void gemm_ln_kernel(const float* __restrict__ X, int t, int O, int dst) {
    const float* W = (O == C_) ? g_Wq : g_Wkv;
    const float* bias = (O == C_) ? g_bq : g_bkv;
    const float* rsum = (O == C_) ? g_rsq : g_rskv;
    float* Y = buf_sel(dst);
    int b = blockIdx.z;
    int pBase = blockIdx.x * 64, oBase = blockIdx.y * 64;
    const float* Xb = X + (size_t)b * C_ * HW_;
    __shared__ float sW[16][64];
    __shared__ float sX[16][64];
    int tid = threadIdx.x;
    int tx = tid & 15, ty = tid >> 4;
    float acc[4][4] = {};
    for (int k0 = 0; k0 < C_; k0 += 16) {
        {
            int o = oBase + (tid >> 2);
            int kk = (tid & 3) << 2;
            float4 wv = *reinterpret_cast<const float4*>(W + (size_t)o * C_ + k0 + kk);
            sW[kk + 0][o - oBase] = wv.x;
            sW[kk + 1][o - oBase] = wv.y;
            sW[kk + 2][o - oBase] = wv.z;
            sW[kk + 3][o - oBase] = wv.w;
        }
#pragma unroll
        for (int it = 0; it < 4; it++) {
            int kk = (tid >> 6) + it * 4;
            int pp = tid & 63;
            sX[kk][pp] = Xb[(size_t)(k0 + kk) * HW_ + pBase + pp];
        }
        __syncthreads();
#pragma unroll
        for (int kk = 0; kk < 16; kk++) {
            float4 wv = *reinterpret_cast<const float4*>(&sW[kk][ty << 2]);
            float4 xv = *reinterpret_cast<const float4*>(&sX[kk][tx << 2]);
            float wr[4] = {wv.x, wv.y, wv.z, wv.w};
            float xr[4] = {xv.x, xv.y, xv.z, xv.w};
#pragma unroll
            for (int r = 0; r < 4; r++)
#pragma unroll
                for (int c = 0; c < 4; c++) acc[r][c] += wr[r] * xr[c];
        }
        __syncthreads();
    }
    const float* mub = g_mu + (size_t)(t * B_ + b) * HW_;
    const float* ivb = g_rstd + (size_t)(t * B_ + b) * HW_;
    float m[4], iv[4];
#pragma unroll
    for (int c = 0; c < 4; c++) {
        int p = pBase + (tx << 2) + c;
        m[c] = mub[p];
        iv[c] = ivb[p];
    }
#pragma unroll
    for (int r = 0; r < 4; r++) {
        int o = oBase + (ty << 2) + r;
        float rs = rsum[o], bo = bias[o];
        float* Yo = Y + ((size_t)b * O + o) * HW_ + pBase + (tx << 2);
        float4 ov;
        ov.x = iv[0] * (acc[r][0] - m[0] * rs) + bo;
        ov.y = iv[1] * (acc[r][1] - m[1] * rs) + bo;
        ov.z = iv[2] * (acc[r][2] - m[2] * rs) + bo;
        ov.w = iv[3] * (acc[r][3] - m[3] * rs) + bo;
        *reinterpret_cast<float4*>(Yo) = ov;
    }
}

// ---------------- depthwise 3x3, SAME, with mode-specific epilogue -----------
// mode 0: +bias   mode 1: gelu(tanh approx), no bias   mode 2: +extra (hx), no bias
__global__ void dwconv_kernel(int src, const float* __restrict__ wDW, const float* __restrict__ bias,
                              int dst0, int dst1, int Csplit, int Ctot, int mode,
                              const float* __restrict__ extra) {
    const float* X = buf_sel(src);
    int c = blockIdx.y, b = blockIdx.z;
    int p = blockIdx.x * 256 + threadIdx.x;
    int i = p >> 7, j = p & 127;
    const float* Xc = X + ((size_t)(b * Ctot + c)) * HW_;
    float wk[9];
#pragma unroll
    for (int t = 0; t < 9; t++) wk[t] = __ldg(wDW + (size_t)c * 9 + t);
    float s = 0.f;
#pragma unroll
    for (int di = -1; di <= 1; di++) {
        int ii = i + di;
        if (ii < 0 || ii >= H_) continue;
#pragma unroll
        for (int dj = -1; dj <= 1; dj++) {
            int jj = j + dj;
            if (jj < 0 || jj >= W_) continue;
            s += wk[(di + 1) * 3 + (dj + 1)] * Xc[ii * W_ + jj];
        }
    }
    if (mode == 0) {
        s += bias[c];
    } else if (mode == 1) {
        float x3 = s * s * s;
        s = 0.5f * s * (1.f + tanhf(0.7978845608028654f * (s + 0.044715f * x3)));
    } else {
        s += extra[((size_t)(b * C_ + c)) * HW_ + p];
    }
    float* Y;
    if (c < Csplit)
        Y = buf_sel(dst0) + ((size_t)(b * Csplit + c)) * HW_ + p;
    else
        Y = buf_sel(dst1) + ((size_t)(b * (Ctot - Csplit) + (c - Csplit))) * HW_ + p;
    *Y = s;
}

// ---------------- per-(b,c) L2 norm scales for q and k -----------------------
__global__ void norm_kernel() {
    int z = blockIdx.z, b = blockIdx.y, c = blockIdx.x;
    const float* X = (z == 0 ? g_q : g_k) + ((size_t)(b * C_ + c)) * HW_;
    int tid = threadIdx.x;
    float ss = 0.f;
    for (int t = tid; t < HW_; t += 256) {
        float v = X[t];
        ss += v * v;
    }
    __shared__ float sh[256];
    sh[tid] = ss;
    __syncthreads();
    for (int s = 128; s > 0; s >>= 1) {
        if (tid < s) sh[tid] += sh[tid + s];
        __syncthreads();
    }
    if (tid == 0) {
        float n = sqrtf(sh[0]);
        g_scale[(z * B_ + b) * C_ + c] = 1.f / fmaxf(n, 1e-12f);
    }
}

// ---------------- gram: split-K raw dot products q[i,:]·k[j,:] ----------------
__global__ void gram_kernel() {
    int seg = blockIdx.x, h = blockIdx.y, b = blockIdx.z;
    __shared__ float sq[32][65];
    __shared__ float sk[32][65];
    const float* Q = g_q + ((size_t)(b * C_ + h * HD_)) * HW_;
    const float* K = g_k + ((size_t)(b * C_ + h * HD_)) * HW_;
    int tid = threadIdx.x;
    int i = tid >> 3;
    int j0 = (tid & 7) << 2;
    float acc[4] = {0.f, 0.f, 0.f, 0.f};
    int n0 = seg * 1024;
    for (int ch = 0; ch < 16; ch++) {
        int base = n0 + ch * 64;
#pragma unroll
        for (int t = 0; t < 8; t++) {
            int idx = tid + t * 256;
            int row = idx >> 6, col = idx & 63;
            sq[row][col] = Q[(size_t)row * HW_ + base + col];
            sk[row][col] = K[(size_t)row * HW_ + base + col];
        }
        __syncthreads();
#pragma unroll 8
        for (int n = 0; n < 64; n++) {
            float qv = sq[i][n];
            acc[0] += qv * sk[j0 + 0][n];
            acc[1] += qv * sk[j0 + 1][n];
            acc[2] += qv * sk[j0 + 2][n];
            acc[3] += qv * sk[j0 + 3][n];
        }
        __syncthreads();
    }
    int baseo = (((b * HEADS_ + h) * 16 + seg) * 32 + i) * 32 + j0;
    g_part[baseo + 0] = acc[0];
    g_part[baseo + 1] = acc[1];
    g_part[baseo + 2] = acc[2];
    g_part[baseo + 3] = acc[3];
}

// ---------------- reduce partials, apply norm scales + temperature, softmax --
__global__ void softmax_kernel(const float* __restrict__ temp) {
    int bh = blockIdx.x;
    int b = bh >> 3, h = bh & 7;
    int i = threadIdx.x;  // 32 threads, one row each
    float qs = g_scale[b * C_ + h * HD_ + i];
    float T = __ldg(temp + h);
    float v[32];
    float mx = -1e30f;
#pragma unroll 4
    for (int j = 0; j < 32; j++) {
        float s = 0.f;
        for (int seg = 0; seg < 16; seg++)
            s += g_part[((bh * 16 + seg) * 32 + i) * 32 + j];
        float ks = g_scale[(B_ + b) * C_ + h * HD_ + j];
        float val = s * qs * ks * T;
        v[j] = val;
        mx = fmaxf(mx, val);
    }
    float sum = 0.f;
#pragma unroll
    for (int j = 0; j < 32; j++) {
        v[j] = expf(v[j] - mx);
        sum += v[j];
    }
    float inv = 1.f / sum;
#pragma unroll
    for (int j = 0; j < 32; j++) g_attn[bh * 1024 + i * 32 + j] = v[j] * inv;
}

// ---------------- M[b] = ao_w @ blockdiag(attn[b]) ---------------------------
__global__ void buildM_kernel(const float* __restrict__ ao_w) {
    int h = blockIdx.x, b = blockIdx.y;
    int tid = threadIdx.x;  // 256 threads, o = tid
    __shared__ float sa[32][33];
#pragma unroll
    for (int t = 0; t < 4; t++) {
        int idx = tid + t * 256;
        sa[idx >> 5][idx & 31] = g_attn[(b * HEADS_ + h) * 1024 + idx];
    }
    __syncthreads();
    float wreg[32];
#pragma unroll
    for (int c = 0; c < 32; c++) wreg[c] = ao_w[(size_t)tid * C_ + h * HD_ + c];
#pragma unroll 4
    for (int d = 0; d < 32; d++) {
        float m = 0.f;
#pragma unroll
        for (int c = 0; c < 32; c++) m += wreg[c] * sa[c][d];
        g_M[((size_t)(b * C_) + tid) * C_ + h * HD_ + d] = m;
    }
}

// ---------------- final: out = M[b] @ v + ao_b + (p_emb + hx) ----------------
__global__ void gemm_final_kernel(const float* __restrict__ ao_b, float* __restrict__ out) {
    int b = blockIdx.z;
    const float* W = g_M + (size_t)b * C_ * C_;
    const float* Xb = g_v + (size_t)b * C_ * HW_;
    const float* pemb = g_bufB + (size_t)b * C_ * HW_;
    int pBase = blockIdx.x * 64, oBase = blockIdx.y * 64;
    __shared__ float sW[16][64];
    __shared__ float sX[16][64];
    int tid = threadIdx.x;
    int tx = tid & 15, ty = tid >> 4;
    float acc[4][4] = {};
    for (int k0 = 0; k0 < C_; k0 += 16) {
        {
            int o = oBase + (tid >> 2);
            int kk = (tid & 3) << 2;
            float4 wv = *reinterpret_cast<const float4*>(W + (size_t)o * C_ + k0 + kk);
            sW[kk + 0][o - oBase] = wv.x;
            sW[kk + 1][o - oBase] = wv.y;
            sW[kk + 2][o - oBase] = wv.z;
            sW[kk + 3][o - oBase] = wv.w;
        }
#pragma unroll
        for (int it = 0; it < 4; it++) {
            int kk = (tid >> 6) + it * 4;
            int pp = tid & 63;
            sX[kk][pp] = Xb[(size_t)(k0 + kk) * HW_ + pBase + pp];
        }
        __syncthreads();
#pragma unroll
        for (int kk = 0; kk < 16; kk++) {
            float4 wv = *reinterpret_cast<const float4*>(&sW[kk][ty << 2]);
            float4 xv = *reinterpret_cast<const float4*>(&sX[kk][tx << 2]);
            float wr[4] = {wv.x, wv.y, wv.z, wv.w};
            float xr[4] = {xv.x, xv.y, xv.z, xv.w};
#pragma unroll
            for (int r = 0; r < 4; r++)
#pragma unroll
                for (int c = 0; c < 4; c++) acc[r][c] += wr[r] * xr[c];
        }
        __syncthreads();
    }
#pragma unroll
    for (int r = 0; r < 4; r++) {
        int o = oBase + (ty << 2) + r;
        float bo = ao_b[o];
        const float* pe = pemb + (size_t)o * HW_ + pBase + (tx << 2);
        float* Yo = out + ((size_t)b * C_ + o) * HW_ + pBase + (tx << 2);
        float4 pv = *reinterpret_cast<const float4*>(pe);
        float4 ov;
        ov.x = acc[r][0] + bo + pv.x;
        ov.y = acc[r][1] + bo + pv.y;
        ov.z = acc[r][2] + bo + pv.z;
        ov.w = acc[r][3] + bo + pv.w;
        *reinterpret_cast<float4*>(Yo) = ov;
    }
}

// -----------------------------------------------------------------------------
extern "C" void kernel_launch(void* const* d_in, const int* in_sizes, int n_in,
                              void* d_out, int out_size) {
    const float* x = (const float*)d_in[0];
    const float* hx = (const float*)d_in[1];
    const float* ln1_w = (const float*)d_in[2];
    const float* ln1_b = (const float*)d_in[3];
    const float* ln2_w = (const float*)d_in[4];
    const float* ln2_b = (const float*)d_in[5];
    const float* q_w = (const float*)d_in[6];
    const float* q_b = (const float*)d_in[7];
    const float* q_dw_w = (const float*)d_in[8];
    const float* q_dw_b = (const float*)d_in[9];
    const float* kv_w = (const float*)d_in[10];
    const float* kv_b = (const float*)d_in[11];
    const float* kv_dw_w = (const float*)d_in[12];
    const float* kv_dw_b = (const float*)d_in[13];
    const float* ao_w = (const float*)d_in[14];
    const float* ao_b = (const float*)d_in[15];
    const float* pe1_w = (const float*)d_in[16];
    const float* pe2_w = (const float*)d_in[17];
    const float* temperature = (const float*)d_in[18];
    float* out = (float*)d_out;

    // 1. fold LN gamma/beta into conv1x1 weights + row sums
    prep_w_kernel<<<3 * C_, 256>>>(q_w, q_b, ln1_w, ln1_b, kv_w, kv_b, ln2_w, ln2_b);
    // 2. per-pixel LN stats for x and hx
    ln_stats_kernel<<<dim3(HW_ / 256, B_, 2), 256>>>(x, hx);
    // 3. q_pre = conv1x1(ln(x)) -> bufA ; kv_pre = conv1x1(ln(hx)) -> bufB
    gemm_ln_kernel<<<dim3(HW_ / 64, C_ / 64, B_), 256>>>(x, 0, C_, 0);
    gemm_ln_kernel<<<dim3(HW_ / 64, 2 * C_ / 64, B_), 256>>>(hx, 1, 2 * C_, 1);
    // 4. depthwise convs: q ; kv split into k/v
    dwconv_kernel<<<dim3(HW_ / 256, C_, B_), 256>>>(0, q_dw_w, q_dw_b, 2, 2, C_, C_, 0, nullptr);
    dwconv_kernel<<<dim3(HW_ / 256, 2 * C_, B_), 256>>>(1, kv_dw_w, kv_dw_b, 3, 4, C_, 2 * C_, 0, nullptr);
    // 5. positional branch: t1 = gelu(dw(v, pe1)) -> bufA ; p_emb+hx = dw(t1, pe2)+hx -> bufB
    dwconv_kernel<<<dim3(HW_ / 256, C_, B_), 256>>>(4, pe1_w, nullptr, 0, 0, C_, C_, 1, nullptr);
    dwconv_kernel<<<dim3(HW_ / 256, C_, B_), 256>>>(0, pe2_w, nullptr, 1, 1, C_, C_, 2, hx);
    // 6. q/k row norms
    norm_kernel<<<dim3(C_, B_, 2), 256>>>();
    // 7. split-K gram, then fused scale+temperature+softmax
    gram_kernel<<<dim3(16, HEADS_, B_), 256>>>();
    softmax_kernel<<<B_ * HEADS_, 32>>>(temperature);
    // 8. fold attn into output projection, then final fused GEMM
    buildM_kernel<<<dim3(HEADS_, B_), 256>>>(ao_w);
    gemm_final_kernel<<<dim3(HW_ / 64, C_ / 64, B_), 256>>>(ao_b, out);
}

// round 2
// speedup vs baseline: 1.6720x; 1.6720x over previous
#include <cuda_runtime.h>
#include <math.h>

#define B_ 8
#define C_ 256
#define H_ 128
#define W_ 128
#define HW_ 16384
#define HEADS_ 8
#define HD_ 32

// ---------------- scratch (device globals; no allocation allowed) ------------
__device__ float g_bufA[B_ * C_ * HW_];          // q_pre, later t1 (gelu(dw(v,pe1)))
__device__ float g_bufB[B_ * 2 * C_ * HW_];      // kv_pre, later (first half) p_emb + hx
__device__ float g_q[B_ * C_ * HW_];
__device__ float g_k[B_ * C_ * HW_];
__device__ float g_v[B_ * C_ * HW_];
__device__ float g_Wq[C_ * C_];                  // q_w * ln1_w (folded)
__device__ float g_Wkv[2 * C_ * C_];             // kv_w * ln2_w (folded)
__device__ float g_bq[C_];
__device__ float g_bkv[2 * C_];
__device__ float g_rsq[C_];                      // row sums of folded weights
__device__ float g_rskv[2 * C_];
__device__ float g_mu[2 * B_ * HW_];             // LN stats: [tensor(x/hx)][b][p]
__device__ float g_rstd[2 * B_ * HW_];
__device__ float g_scale[2 * B_ * C_];           // 1/max(||row||,eps) for q (z=0), k (z=1)
__device__ float g_part[B_ * HEADS_ * 16 * 32 * 32];  // split-K gram partials
__device__ float g_attn[B_ * HEADS_ * 32 * 32];
__device__ float g_M[B_ * C_ * C_];              // ao_w @ blockdiag(attn) per batch

__device__ __forceinline__ float* buf_sel(int id) {
    switch (id) {
        case 0: return g_bufA;
        case 1: return g_bufB;
        case 2: return g_q;
        case 3: return g_k;
        case 4: return g_v;
    }
    return g_bufA;
}

__device__ __forceinline__ unsigned f2tf32(float f) {
    unsigned u;
    asm volatile("cvt.rna.tf32.f32 %0, %1;" : "=r"(u) : "f"(f));
    return u;
}

__device__ __forceinline__ void mma_tf32(float* c, const unsigned* a, unsigned b0, unsigned b1) {
    asm volatile(
        "mma.sync.aligned.m16n8k8.row.col.f32.tf32.tf32.f32 "
        "{%0,%1,%2,%3}, {%4,%5,%6,%7}, {%8,%9}, {%0,%1,%2,%3};\n"
        : "+f"(c[0]), "+f"(c[1]), "+f"(c[2]), "+f"(c[3])
        : "r"(a[0]), "r"(a[1]), "r"(a[2]), "r"(a[3]), "r"(b0), "r"(b1));
}

// ---------------- weight prep: fold LN gamma/beta into conv1x1 ---------------
__global__ void prep_w_kernel(const float* __restrict__ qw, const float* __restrict__ qb,
                              const float* __restrict__ ln1w, const float* __restrict__ ln1b,
                              const float* __restrict__ kvw, const float* __restrict__ kvb,
                              const float* __restrict__ ln2w, const float* __restrict__ ln2b) {
    int r = blockIdx.x;
    int tid = threadIdx.x;  // 256 threads = one per input channel
    const float *w, *lnw, *lnb;
    float cb;
    float *dW, *dB, *dR;
    if (r < C_) {
        int o = r;
        w = qw + (size_t)o * C_; lnw = ln1w; lnb = ln1b; cb = qb[o];
        dW = g_Wq + (size_t)o * C_; dB = g_bq + o; dR = g_rsq + o;
    } else {
        int o = r - C_;
        w = kvw + (size_t)o * C_; lnw = ln2w; lnb = ln2b; cb = kvb[o];
        dW = g_Wkv + (size_t)o * C_; dB = g_bkv + o; dR = g_rskv + o;
    }
    float wv = w[tid];
    float we = wv * lnw[tid];
    dW[tid] = we;
    __shared__ float sh1[256], sh2[256];
    sh1[tid] = we;
    sh2[tid] = wv * lnb[tid];
    __syncthreads();
    for (int s = 128; s > 0; s >>= 1) {
        if (tid < s) { sh1[tid] += sh1[tid + s]; sh2[tid] += sh2[tid + s]; }
        __syncthreads();
    }
    if (tid == 0) { *dR = sh1[0]; *dB = cb + sh2[0]; }
}

// ---------------- per-pixel LN stats over channels ---------------------------
__global__ void ln_stats_kernel(const float* __restrict__ x, const float* __restrict__ hx) {
    int t = blockIdx.z, b = blockIdx.y;
    int p = blockIdx.x * 256 + threadIdx.x;
    const float* X = (t == 0 ? x : hx) + (size_t)b * C_ * HW_ + p;
    float s = 0.f, s2 = 0.f;
#pragma unroll 4
    for (int c = 0; c < C_; c++) {
        float v = X[(size_t)c * HW_];
        s += v; s2 += v * v;
    }
    float mu = s * (1.f / C_);
    float var = s2 * (1.f / C_) - mu * mu;
    int idx = (t * B_ + b) * HW_ + p;
    g_mu[idx] = mu;
    g_rstd[idx] = rsqrtf(var + 1e-5f);
}

// ================== tensor-core GEMM (tf32 mma.sync) =========================
// Block tile 128(o) x 128(p), K chunks of 32, 8 warps each computing 64x32.
// sA: [128][36] (o-major, padded), sB: [32][136] (k-major, padded).
// mode 0: LN epilogue  Y = rstd*(acc - mu*rsum) + bias        (Y = buf dst)
// mode 1: final        Y = acc + ao_b[o] + pemb[o,p]          (Y = out)
struct GemmArgs {
    const float* X;      // [b][k][p] global (k stride HW_)
    const float* Wg;     // [o][k] global, row stride C_
    const float* bias;
    const float* rsum;   // mode 0 only
    const float* mu;     // mode 0: g_mu + t*B_*HW_
    const float* rstd;
    const float* pemb;   // mode 1 only (per-batch stride C_*HW_)
    float* Y;
    int O;
    int mode;
    int perBatchW;       // 1 if W has per-batch stride O*C_ (g_M), else 0
};

__global__ __launch_bounds__(256) void gemm_tc_kernel(GemmArgs ga) {
    __shared__ unsigned sA[128 * 36];
    __shared__ unsigned sB[32 * 136];
    int b = blockIdx.z;
    int pBase = blockIdx.x * 128;
    int oBase = blockIdx.y * 128;
    int tid = threadIdx.x;
    int wid = tid >> 5, lane = tid & 31;
    int g = lane >> 2, tig = lane & 3;
    int oW = (wid >> 2) * 64;   // warp o offset within block tile
    int pW = (wid & 3) * 32;    // warp p offset

    const float* Xb = ga.X + (size_t)b * C_ * HW_;
    const float* Wb = ga.Wg + (ga.perBatchW ? (size_t)b * ga.O * C_ : 0);

    float acc[4][4][4] = {};

    for (int k0 = 0; k0 < C_; k0 += 32) {
        // load A tile: 128 o x 32 k  (4 float4 per thread)
#pragma unroll
        for (int i = 0; i < 4; i++) {
            int idx = tid + i * 256;          // 0..1023
            int o = idx >> 3;                 // 0..127
            int kq = idx & 7;                 // 0..7 -> k = kq*4
            float4 wv = *reinterpret_cast<const float4*>(
                Wb + (size_t)(oBase + o) * C_ + k0 + kq * 4);
            unsigned* dst = &sA[o * 36 + kq * 4];
            dst[0] = f2tf32(wv.x); dst[1] = f2tf32(wv.y);
            dst[2] = f2tf32(wv.z); dst[3] = f2tf32(wv.w);
        }
        // load B tile: 32 k x 128 p  (4 float4 per thread)
#pragma unroll
        for (int i = 0; i < 4; i++) {
            int idx = tid + i * 256;
            int k = idx >> 5;                 // 0..31
            int pq = idx & 31;                // p = pq*4
            float4 xv = *reinterpret_cast<const float4*>(
                Xb + (size_t)(k0 + k) * HW_ + pBase + pq * 4);
            unsigned* dst = &sB[k * 136 + pq * 4];
            dst[0] = f2tf32(xv.x); dst[1] = f2tf32(xv.y);
            dst[2] = f2tf32(xv.z); dst[3] = f2tf32(xv.w);
        }
        __syncthreads();
#pragma unroll
        for (int s = 0; s < 32; s += 8) {
            unsigned afr[4][4];
#pragma unroll
            for (int mt = 0; mt < 4; mt++) {
                int ro = oW + mt * 16 + g;
                afr[mt][0] = sA[ro * 36 + s + tig];
                afr[mt][1] = sA[(ro + 8) * 36 + s + tig];
                afr[mt][2] = sA[ro * 36 + s + tig + 4];
                afr[mt][3] = sA[(ro + 8) * 36 + s + tig + 4];
            }
#pragma unroll
            for (int nt = 0; nt < 4; nt++) {
                int cp = pW + nt * 8 + g;
                unsigned b0 = sB[(s + tig) * 136 + cp];
                unsigned b1 = sB[(s + tig + 4) * 136 + cp];
#pragma unroll
                for (int mt = 0; mt < 4; mt++)
                    mma_tf32(acc[mt][nt], afr[mt], b0, b1);
            }
        }
        __syncthreads();
    }

    // ------- epilogue -------
    if (ga.mode == 0) {
        const float* mub = ga.mu + (size_t)b * HW_;
        const float* ivb = ga.rstd + (size_t)b * HW_;
        float2 mu2[4], iv2[4];
#pragma unroll
        for (int nt = 0; nt < 4; nt++) {
            int p = pBase + pW + nt * 8 + 2 * tig;
            mu2[nt] = *reinterpret_cast<const float2*>(mub + p);
            iv2[nt] = *reinterpret_cast<const float2*>(ivb + p);
        }
#pragma unroll
        for (int mt = 0; mt < 4; mt++) {
            int o0 = oBase + oW + mt * 16 + g;
            int o1 = o0 + 8;
            float rs0 = ga.rsum[o0], b0v = ga.bias[o0];
            float rs1 = ga.rsum[o1], b1v = ga.bias[o1];
#pragma unroll
            for (int nt = 0; nt < 4; nt++) {
                int p = pBase + pW + nt * 8 + 2 * tig;
                float2 r0, r1;
                r0.x = iv2[nt].x * (acc[mt][nt][0] - mu2[nt].x * rs0) + b0v;
                r0.y = iv2[nt].y * (acc[mt][nt][1] - mu2[nt].y * rs0) + b0v;
                r1.x = iv2[nt].x * (acc[mt][nt][2] - mu2[nt].x * rs1) + b1v;
                r1.y = iv2[nt].y * (acc[mt][nt][3] - mu2[nt].y * rs1) + b1v;
                *reinterpret_cast<float2*>(ga.Y + ((size_t)b * ga.O + o0) * HW_ + p) = r0;
                *reinterpret_cast<float2*>(ga.Y + ((size_t)b * ga.O + o1) * HW_ + p) = r1;
            }
        }
    } else {
        const float* pe = ga.pemb + (size_t)b * C_ * HW_;
#pragma unroll
        for (int mt = 0; mt < 4; mt++) {
            int o0 = oBase + oW + mt * 16 + g;
            int o1 = o0 + 8;
            float b0v = ga.bias[o0], b1v = ga.bias[o1];
#pragma unroll
            for (int nt = 0; nt < 4; nt++) {
                int p = pBase + pW + nt * 8 + 2 * tig;
                float2 p0 = *reinterpret_cast<const float2*>(pe + (size_t)o0 * HW_ + p);
                float2 p1 = *reinterpret_cast<const float2*>(pe + (size_t)o1 * HW_ + p);
                float2 r0, r1;
                r0.x = acc[mt][nt][0] + b0v + p0.x;
                r0.y = acc[mt][nt][1] + b0v + p0.y;
                r1.x = acc[mt][nt][2] + b1v + p1.x;
                r1.y = acc[mt][nt][3] + b1v + p1.y;
                *reinterpret_cast<float2*>(ga.Y + ((size_t)b * C_ + o0) * HW_ + p) = r0;
                *reinterpret_cast<float2*>(ga.Y + ((size_t)b * C_ + o1) * HW_ + p) = r1;
            }
        }
    }
}

// ---------------- depthwise 3x3, SAME, with mode-specific epilogue -----------
// mode 0: +bias   mode 1: gelu(tanh approx), no bias   mode 2: +extra (hx), no bias
__global__ void dwconv_kernel(int src, const float* __restrict__ wDW, const float* __restrict__ bias,
                              int dst0, int dst1, int Csplit, int Ctot, int mode,
                              const float* __restrict__ extra) {
    const float* X = buf_sel(src);
    int c = blockIdx.y, b = blockIdx.z;
    int p = blockIdx.x * 256 + threadIdx.x;
    int i = p >> 7, j = p & 127;
    const float* Xc = X + ((size_t)(b * Ctot + c)) * HW_;
    float wk[9];
#pragma unroll
    for (int t = 0; t < 9; t++) wk[t] = __ldg(wDW + (size_t)c * 9 + t);
    float s = 0.f;
#pragma unroll
    for (int di = -1; di <= 1; di++) {
        int ii = i + di;
        if (ii < 0 || ii >= H_) continue;
#pragma unroll
        for (int dj = -1; dj <= 1; dj++) {
            int jj = j + dj;
            if (jj < 0 || jj >= W_) continue;
            s += wk[(di + 1) * 3 + (dj + 1)] * Xc[ii * W_ + jj];
        }
    }
    if (mode == 0) {
        s += bias[c];
    } else if (mode == 1) {
        float x3 = s * s * s;
        s = 0.5f * s * (1.f + tanhf(0.7978845608028654f * (s + 0.044715f * x3)));
    } else {
        s += extra[((size_t)(b * C_ + c)) * HW_ + p];
    }
    float* Y;
    if (c < Csplit)
        Y = buf_sel(dst0) + ((size_t)(b * Csplit + c)) * HW_ + p;
    else
        Y = buf_sel(dst1) + ((size_t)(b * (Ctot - Csplit) + (c - Csplit))) * HW_ + p;
    *Y = s;
}

// ---------------- per-(b,c) L2 norm scales for q and k -----------------------
__global__ void norm_kernel() {
    int z = blockIdx.z, b = blockIdx.y, c = blockIdx.x;
    const float* X = (z == 0 ? g_q : g_k) + ((size_t)(b * C_ + c)) * HW_;
    int tid = threadIdx.x;
    float ss = 0.f;
    for (int t = tid; t < HW_; t += 256) {
        float v = X[t];
        ss += v * v;
    }
    __shared__ float sh[256];
    sh[tid] = ss;
    __syncthreads();
    for (int s = 128; s > 0; s >>= 1) {
        if (tid < s) sh[tid] += sh[tid + s];
        __syncthreads();
    }
    if (tid == 0) {
        float n = sqrtf(sh[0]);
        g_scale[(z * B_ + b) * C_ + c] = 1.f / fmaxf(n, 1e-12f);
    }
}

// ---------------- gram: split-K raw dot products q[i,:]·k[j,:] ----------------
__global__ void gram_kernel() {
    int seg = blockIdx.x, h = blockIdx.y, b = blockIdx.z;
    __shared__ float sq[32][65];
    __shared__ float sk[32][65];
    const float* Q = g_q + ((size_t)(b * C_ + h * HD_)) * HW_;
    const float* K = g_k + ((size_t)(b * C_ + h * HD_)) * HW_;
    int tid = threadIdx.x;
    int i = tid >> 3;
    int j0 = (tid & 7) << 2;
    float acc[4] = {0.f, 0.f, 0.f, 0.f};
    int n0 = seg * 1024;
    for (int ch = 0; ch < 16; ch++) {
        int base = n0 + ch * 64;
#pragma unroll
        for (int t = 0; t < 8; t++) {
            int idx = tid + t * 256;
            int row = idx >> 6, col = idx & 63;
            sq[row][col] = Q[(size_t)row * HW_ + base + col];
            sk[row][col] = K[(size_t)row * HW_ + base + col];
        }
        __syncthreads();
#pragma unroll 8
        for (int n = 0; n < 64; n++) {
            float qv = sq[i][n];
            acc[0] += qv * sk[j0 + 0][n];
            acc[1] += qv * sk[j0 + 1][n];
            acc[2] += qv * sk[j0 + 2][n];
            acc[3] += qv * sk[j0 + 3][n];
        }
        __syncthreads();
    }
    int baseo = (((b * HEADS_ + h) * 16 + seg) * 32 + i) * 32 + j0;
    g_part[baseo + 0] = acc[0];
    g_part[baseo + 1] = acc[1];
    g_part[baseo + 2] = acc[2];
    g_part[baseo + 3] = acc[3];
}

// ---------------- reduce partials, apply norm scales + temperature, softmax --
__global__ void softmax_kernel(const float* __restrict__ temp) {
    int bh = blockIdx.x;
    int b = bh >> 3, h = bh & 7;
    int i = threadIdx.x;  // 32 threads, one row each
    float qs = g_scale[b * C_ + h * HD_ + i];
    float T = __ldg(temp + h);
    float v[32];
    float mx = -1e30f;
#pragma unroll 4
    for (int j = 0; j < 32; j++) {
        float s = 0.f;
        for (int seg = 0; seg < 16; seg++)
            s += g_part[((bh * 16 + seg) * 32 + i) * 32 + j];
        float ks = g_scale[(B_ + b) * C_ + h * HD_ + j];
        float val = s * qs * ks * T;
        v[j] = val;
        mx = fmaxf(mx, val);
    }
    float sum = 0.f;
#pragma unroll
    for (int j = 0; j < 32; j++) {
        v[j] = expf(v[j] - mx);
        sum += v[j];
    }
    float inv = 1.f / sum;
#pragma unroll
    for (int j = 0; j < 32; j++) g_attn[bh * 1024 + i * 32 + j] = v[j] * inv;
}

// ---------------- M[b] = ao_w @ blockdiag(attn[b]) ---------------------------
__global__ void buildM_kernel(const float* __restrict__ ao_w) {
    int h = blockIdx.x, b = blockIdx.y;
    int tid = threadIdx.x;  // 256 threads, o = tid
    __shared__ float sa[32][33];
#pragma unroll
    for (int t = 0; t < 4; t++) {
        int idx = tid + t * 256;
        sa[idx >> 5][idx & 31] = g_attn[(b * HEADS_ + h) * 1024 + idx];
    }
    __syncthreads();
    float wreg[32];
#pragma unroll
    for (int c = 0; c < 32; c++) wreg[c] = ao_w[(size_t)tid * C_ + h * HD_ + c];
#pragma unroll 4
    for (int d = 0; d < 32; d++) {
        float m = 0.f;
#pragma unroll
        for (int c = 0; c < 32; c++) m += wreg[c] * sa[c][d];
        g_M[((size_t)(b * C_) + tid) * C_ + h * HD_ + d] = m;
    }
}

// -----------------------------------------------------------------------------
extern "C" void kernel_launch(void* const* d_in, const int* in_sizes, int n_in,
                              void* d_out, int out_size) {
    const float* x = (const float*)d_in[0];
    const float* hx = (const float*)d_in[1];
    const float* ln1_w = (const float*)d_in[2];
    const float* ln1_b = (const float*)d_in[3];
    const float* ln2_w = (const float*)d_in[4];
    const float* ln2_b = (const float*)d_in[5];
    const float* q_w = (const float*)d_in[6];
    const float* q_b = (const float*)d_in[7];
    const float* q_dw_w = (const float*)d_in[8];
    const float* q_dw_b = (const float*)d_in[9];
    const float* kv_w = (const float*)d_in[10];
    const float* kv_b = (const float*)d_in[11];
    const float* kv_dw_w = (const float*)d_in[12];
    const float* kv_dw_b = (const float*)d_in[13];
    const float* ao_w = (const float*)d_in[14];
    const float* ao_b = (const float*)d_in[15];
    const float* pe1_w = (const float*)d_in[16];
    const float* pe2_w = (const float*)d_in[17];
    const float* temperature = (const float*)d_in[18];
    float* out = (float*)d_out;

    // device-global symbol addresses (host side)
    float *p_Wq, *p_Wkv, *p_bq, *p_bkv, *p_rsq, *p_rskv, *p_mu, *p_rstd;
    float *p_bufA, *p_bufB, *p_v, *p_M;
    cudaGetSymbolAddress((void**)&p_Wq, g_Wq);
    cudaGetSymbolAddress((void**)&p_Wkv, g_Wkv);
    cudaGetSymbolAddress((void**)&p_bq, g_bq);
    cudaGetSymbolAddress((void**)&p_bkv, g_bkv);
    cudaGetSymbolAddress((void**)&p_rsq, g_rsq);
    cudaGetSymbolAddress((void**)&p_rskv, g_rskv);
    cudaGetSymbolAddress((void**)&p_mu, g_mu);
    cudaGetSymbolAddress((void**)&p_rstd, g_rstd);
    cudaGetSymbolAddress((void**)&p_bufA, g_bufA);
    cudaGetSymbolAddress((void**)&p_bufB, g_bufB);
    cudaGetSymbolAddress((void**)&p_v, g_v);
    cudaGetSymbolAddress((void**)&p_M, g_M);

    // 1. fold LN gamma/beta into conv1x1 weights + row sums
    prep_w_kernel<<<3 * C_, 256>>>(q_w, q_b, ln1_w, ln1_b, kv_w, kv_b, ln2_w, ln2_b);
    // 2. per-pixel LN stats for x and hx
    ln_stats_kernel<<<dim3(HW_ / 256, B_, 2), 256>>>(x, hx);

    // 3. q_pre = conv1x1(ln(x)) -> bufA ; kv_pre = conv1x1(ln(hx)) -> bufB
    {
        GemmArgs ga{};
        ga.X = x; ga.Wg = p_Wq; ga.bias = p_bq; ga.rsum = p_rsq;
        ga.mu = p_mu; ga.rstd = p_rstd; ga.Y = p_bufA; ga.O = C_;
        ga.mode = 0; ga.perBatchW = 0;
        gemm_tc_kernel<<<dim3(HW_ / 128, C_ / 128, B_), 256>>>(ga);
    }
    {
        GemmArgs ga{};
        ga.X = hx; ga.Wg = p_Wkv; ga.bias = p_bkv; ga.rsum = p_rskv;
        ga.mu = p_mu + (size_t)B_ * HW_; ga.rstd = p_rstd + (size_t)B_ * HW_;
        ga.Y = p_bufB; ga.O = 2 * C_; ga.mode = 0; ga.perBatchW = 0;
        gemm_tc_kernel<<<dim3(HW_ / 128, 2 * C_ / 128, B_), 256>>>(ga);
    }

    // 4. depthwise convs: q ; kv split into k/v
    dwconv_kernel<<<dim3(HW_ / 256, C_, B_), 256>>>(0, q_dw_w, q_dw_b, 2, 2, C_, C_, 0, nullptr);
    dwconv_kernel<<<dim3(HW_ / 256, 2 * C_, B_), 256>>>(1, kv_dw_w, kv_dw_b, 3, 4, C_, 2 * C_, 0, nullptr);
    // 5. positional branch: t1 = gelu(dw(v, pe1)) -> bufA ; p_emb+hx = dw(t1, pe2)+hx -> bufB
    dwconv_kernel<<<dim3(HW_ / 256, C_, B_), 256>>>(4, pe1_w, nullptr, 0, 0, C_, C_, 1, nullptr);
    dwconv_kernel<<<dim3(HW_ / 256, C_, B_), 256>>>(0, pe2_w, nullptr, 1, 1, C_, C_, 2, hx);
    // 6. q/k row norms
    norm_kernel<<<dim3(C_, B_, 2), 256>>>();
    // 7. split-K gram, then fused scale+temperature+softmax
    gram_kernel<<<dim3(16, HEADS_, B_), 256>>>();
    softmax_kernel<<<B_ * HEADS_, 32>>>(temperature);
    // 8. fold attn into output projection, then final fused GEMM
    buildM_kernel<<<dim3(HEADS_, B_), 256>>>(ao_w);
    {
        GemmArgs ga{};
        ga.X = p_v; ga.Wg = p_M; ga.bias = ao_b; ga.pemb = p_bufB;
        ga.Y = out; ga.O = C_; ga.mode = 1; ga.perBatchW = 1;
        gemm_tc_kernel<<<dim3(HW_ / 128, C_ / 128, B_), 256>>>(ga);
    }
}

// round 3
// speedup vs baseline: 3.2787x; 1.9609x over previous
#include <cuda_runtime.h>
#include <math.h>
#include <stdint.h>

#define B_ 8
#define C_ 256
#define H_ 128
#define W_ 128
#define HW_ 16384
#define HEADS_ 8
#define HD_ 32
#define GSEG 4

// ---------------- scratch (device globals; no allocation allowed) ------------
__device__ float g_bufA[B_ * C_ * HW_];          // q_pre
__device__ float g_bufB[B_ * 2 * C_ * HW_];      // kv_pre, later (first half) p_emb + hx
__device__ float g_q[B_ * C_ * HW_];
__device__ float g_k[B_ * C_ * HW_];
__device__ float g_v[B_ * C_ * HW_];
__device__ float g_Wq[C_ * C_];
__device__ float g_Wkv[2 * C_ * C_];
__device__ float g_bq[C_];
__device__ float g_bkv[2 * C_];
__device__ float g_rsq[C_];
__device__ float g_rskv[2 * C_];
__device__ float g_ss[2 * B_ * C_];              // sum of squares: z=0 q, z=1 k
__device__ float g_part[B_ * HEADS_ * GSEG * 1024];
__device__ float g_attn[B_ * HEADS_ * 1024];
__device__ float g_M[B_ * C_ * C_];

// ---------------- PTX helpers ------------------------------------------------
__device__ __forceinline__ void mma_tf32(float* c, const unsigned* a, unsigned b0, unsigned b1) {
    asm volatile(
        "mma.sync.aligned.m16n8k8.row.col.f32.tf32.tf32.f32 "
        "{%0,%1,%2,%3}, {%4,%5,%6,%7}, {%8,%9}, {%0,%1,%2,%3};\n"
        : "+f"(c[0]), "+f"(c[1]), "+f"(c[2]), "+f"(c[3])
        : "r"(a[0]), "r"(a[1]), "r"(a[2]), "r"(a[3]), "r"(b0), "r"(b1));
}
__device__ __forceinline__ uint32_t smem_u32(const void* p) {
    return (uint32_t)__cvta_generic_to_shared(p);
}
__device__ __forceinline__ void cp16(uint32_t dst, const void* src) {
    asm volatile("cp.async.cg.shared.global [%0], [%1], 16;\n" :: "r"(dst), "l"(src));
}
__device__ __forceinline__ void cp_commit() { asm volatile("cp.async.commit_group;\n"); }
template <int N>
__device__ __forceinline__ void cp_wait() { asm volatile("cp.async.wait_group %0;\n" ::"n"(N)); }

// ---------------- weight prep: fold LN gamma/beta into conv1x1 ---------------
__global__ void prep_w_kernel(const float* __restrict__ qw, const float* __restrict__ qb,
                              const float* __restrict__ ln1w, const float* __restrict__ ln1b,
                              const float* __restrict__ kvw, const float* __restrict__ kvb,
                              const float* __restrict__ ln2w, const float* __restrict__ ln2b) {
    int r = blockIdx.x;
    int tid = threadIdx.x;
    if (r < 16) g_ss[r * 256 + tid] = 0.f;   // zero sumsq accumulators (4096 floats)
    const float *w, *lnw, *lnb;
    float cb;
    float *dW, *dB, *dR;
    if (r < C_) {
        int o = r;
        w = qw + (size_t)o * C_; lnw = ln1w; lnb = ln1b; cb = qb[o];
        dW = g_Wq + (size_t)o * C_; dB = g_bq + o; dR = g_rsq + o;
    } else {
        int o = r - C_;
        w = kvw + (size_t)o * C_; lnw = ln2w; lnb = ln2b; cb = kvb[o];
        dW = g_Wkv + (size_t)o * C_; dB = g_bkv + o; dR = g_rskv + o;
    }
    float wv = w[tid];
    float we = wv * lnw[tid];
    dW[tid] = we;
    __shared__ float sh1[256], sh2[256];
    sh1[tid] = we;
    sh2[tid] = wv * lnb[tid];
    __syncthreads();
    for (int s = 128; s > 0; s >>= 1) {
        if (tid < s) { sh1[tid] += sh1[tid + s]; sh2[tid] += sh2[tid + s]; }
        __syncthreads();
    }
    if (tid == 0) { *dR = sh1[0]; *dB = cb + sh2[0]; }
}

// ================== tensor-core GEMM (tf32 mma, cp.async 2-stage) ============
// Block tile 128(o) x 128(p). K = 256 in chunks of 32.
// mode 0: LN epilogue (stats computed in-block)   mode 1: +bias +pemb
struct GemmArgs {
    const float* X;      // [b][k][p], k stride HW_
    const float* Wg;     // [o][k], row stride C_
    const float* bias;
    const float* rsum;
    const float* pemb;
    float* Y;
    int O;
    int mode;
    int perBatchW;
};

#define ST_FLOATS 8960   // per stage: A 128*36=4608 + B 32*136=4352

__global__ __launch_bounds__(256, 2) void gemm_tc_kernel(GemmArgs ga) {
    extern __shared__ unsigned sm[];
    __shared__ float s_st[4][128];
    int b = blockIdx.z;
    int pBase = blockIdx.x * 128;
    int oBase = blockIdx.y * 128;
    int tid = threadIdx.x;
    int wid = tid >> 5, lane = tid & 31;
    int g = lane >> 2, tig = lane & 3;
    int oW = (wid >> 2) * 64;
    int pW = (wid & 3) * 32;

    const float* Xb = ga.X + (size_t)b * C_ * HW_;
    const float* Wb = ga.Wg + (ga.perBatchW ? (size_t)b * ga.O * C_ : 0);

    uint32_t smA = smem_u32(sm);

    // issue loads for a stage
    auto load_stage = [&](int st, int k0) {
        uint32_t baseA = smA + st * ST_FLOATS * 4;
        uint32_t baseB = baseA + 4608 * 4;
#pragma unroll
        for (int i = 0; i < 4; i++) {
            int idx = tid + i * 256;
            int o = idx >> 3, kq = idx & 7;
            cp16(baseA + (o * 36 + kq * 4) * 4, Wb + (size_t)(oBase + o) * C_ + k0 + kq * 4);
        }
#pragma unroll
        for (int i = 0; i < 4; i++) {
            int idx = tid + i * 256;
            int k = idx >> 5, pq = idx & 31;
            cp16(baseB + (k * 136 + pq * 4) * 4, Xb + (size_t)(k0 + k) * HW_ + pBase + pq * 4);
        }
        cp_commit();
    };

    float acc[4][4][4] = {};
    float stS = 0.f, stQ = 0.f;
    int pl_stat = tid & 127, kh_stat = tid >> 7;

    load_stage(0, 0);
    for (int kc = 0; kc < 8; kc++) {
        if (kc + 1 < 8) { load_stage((kc + 1) & 1, (kc + 1) * 32); cp_wait<1>(); }
        else cp_wait<0>();
        __syncthreads();
        unsigned* sA = sm + (kc & 1) * ST_FLOATS;
        unsigned* sB = sA + 4608;
        if (ga.mode == 0) {
#pragma unroll
            for (int kk = 0; kk < 16; kk++) {
                float v = __uint_as_float(sB[(kh_stat * 16 + kk) * 136 + pl_stat]);
                stS += v; stQ += v * v;
            }
        }
#pragma unroll
        for (int s = 0; s < 32; s += 8) {
            unsigned afr[4][4];
#pragma unroll
            for (int mt = 0; mt < 4; mt++) {
                int ro = oW + mt * 16 + g;
                afr[mt][0] = sA[ro * 36 + s + tig];
                afr[mt][1] = sA[(ro + 8) * 36 + s + tig];
                afr[mt][2] = sA[ro * 36 + s + tig + 4];
                afr[mt][3] = sA[(ro + 8) * 36 + s + tig + 4];
            }
#pragma unroll
            for (int nt = 0; nt < 4; nt++) {
                int cp = pW + nt * 8 + g;
                unsigned b0 = sB[(s + tig) * 136 + cp];
                unsigned b1 = sB[(s + tig + 4) * 136 + cp];
#pragma unroll
                for (int mt = 0; mt < 4; mt++)
                    mma_tf32(acc[mt][nt], afr[mt], b0, b1);
            }
        }
        __syncthreads();
    }

    if (ga.mode == 0) {
        s_st[kh_stat][pl_stat] = stS;
        s_st[2 + kh_stat][pl_stat] = stQ;
        __syncthreads();
        float mu[4][2], iv[4][2];
#pragma unroll
        for (int nt = 0; nt < 4; nt++) {
#pragma unroll
            for (int u = 0; u < 2; u++) {
                int pl = pW + nt * 8 + 2 * tig + u;
                float s0 = s_st[0][pl] + s_st[1][pl];
                float q0 = s_st[2][pl] + s_st[3][pl];
                float m = s0 * (1.f / 256.f);
                float var = q0 * (1.f / 256.f) - m * m;
                mu[nt][u] = m;
                iv[nt][u] = rsqrtf(var + 1e-5f);
            }
        }
#pragma unroll
        for (int mt = 0; mt < 4; mt++) {
            int o0 = oBase + oW + mt * 16 + g;
            int o1 = o0 + 8;
            float rs0 = ga.rsum[o0], b0v = ga.bias[o0];
            float rs1 = ga.rsum[o1], b1v = ga.bias[o1];
#pragma unroll
            for (int nt = 0; nt < 4; nt++) {
                int p = pBase + pW + nt * 8 + 2 * tig;
                float2 r0, r1;
                r0.x = iv[nt][0] * (acc[mt][nt][0] - mu[nt][0] * rs0) + b0v;
                r0.y = iv[nt][1] * (acc[mt][nt][1] - mu[nt][1] * rs0) + b0v;
                r1.x = iv[nt][0] * (acc[mt][nt][2] - mu[nt][0] * rs1) + b1v;
                r1.y = iv[nt][1] * (acc[mt][nt][3] - mu[nt][1] * rs1) + b1v;
                *reinterpret_cast<float2*>(ga.Y + ((size_t)b * ga.O + o0) * HW_ + p) = r0;
                *reinterpret_cast<float2*>(ga.Y + ((size_t)b * ga.O + o1) * HW_ + p) = r1;
            }
        }
    } else {
        const float* pe = ga.pemb + (size_t)b * C_ * HW_;
#pragma unroll
        for (int mt = 0; mt < 4; mt++) {
            int o0 = oBase + oW + mt * 16 + g;
            int o1 = o0 + 8;
            float b0v = ga.bias[o0], b1v = ga.bias[o1];
#pragma unroll
            for (int nt = 0; nt < 4; nt++) {
                int p = pBase + pW + nt * 8 + 2 * tig;
                float2 p0 = *reinterpret_cast<const float2*>(pe + (size_t)o0 * HW_ + p);
                float2 p1 = *reinterpret_cast<const float2*>(pe + (size_t)o1 * HW_ + p);
                float2 r0, r1;
                r0.x = acc[mt][nt][0] + b0v + p0.x;
                r0.y = acc[mt][nt][1] + b0v + p0.y;
                r1.x = acc[mt][nt][2] + b1v + p1.x;
                r1.y = acc[mt][nt][3] + b1v + p1.y;
                *reinterpret_cast<float2*>(ga.Y + ((size_t)b * C_ + o0) * HW_ + p) = r0;
                *reinterpret_cast<float2*>(ga.Y + ((size_t)b * C_ + o1) * HW_ + p) = r1;
            }
        }
    }
}

// ---------------- tiled depthwise 3x3 (+bias), optional sumsq ----------------
// tile: 16 rows x 128 cols per block; 8 outputs/thread
__global__ __launch_bounds__(256) void dw_tiled(const float* __restrict__ X,
                                                const float* __restrict__ wDW,
                                                const float* __restrict__ bias,
                                                float* __restrict__ dst0,
                                                float* __restrict__ dst1,
                                                int Csplit, int Ctot,
                                                float* __restrict__ ssq) {
    __shared__ float st[18][128];
    int b = blockIdx.z, c = blockIdx.y, r0 = blockIdx.x * 16;
    const float* Xc = X + ((size_t)(b * Ctot + c)) * HW_;
    int tid = threadIdx.x;
    for (int i = tid; i < 18 * 32; i += 256) {
        int row = i >> 5, c4 = i & 31;
        int gr = r0 - 1 + row;
        float4 v = make_float4(0.f, 0.f, 0.f, 0.f);
        if (gr >= 0 && gr < H_) v = *reinterpret_cast<const float4*>(Xc + (size_t)gr * W_ + c4 * 4);
        *reinterpret_cast<float4*>(&st[row][c4 * 4]) = v;
    }
    float wk[9];
#pragma unroll
    for (int t = 0; t < 9; t++) wk[t] = __ldg(wDW + (size_t)c * 9 + t);
    float bval = __ldg(bias + c);
    float* D;
    if (c < Csplit) D = dst0 + ((size_t)(b * Csplit + c)) * HW_;
    else D = dst1 + ((size_t)(b * (Ctot - Csplit) + (c - Csplit))) * HW_;
    __syncthreads();
    float ss = 0.f;
#pragma unroll
    for (int t = 0; t < 8; t++) {
        int o = tid + t * 256;
        int row = o >> 7, col = o & 127;
        float s = 0.f;
#pragma unroll
        for (int dr = 0; dr < 3; dr++) {
            const float* Sr = st[row + dr];
            float l = (col > 0) ? Sr[col - 1] : 0.f;
            float m = Sr[col];
            float r = (col < 127) ? Sr[col + 1] : 0.f;
            s += wk[dr * 3 + 0] * l + wk[dr * 3 + 1] * m + wk[dr * 3 + 2] * r;
        }
        s += bval;
        D[(size_t)(r0 + row) * W_ + col] = s;
        ss += s * s;
    }
    if (ssq != nullptr && c < Csplit) {
#pragma unroll
        for (int d = 16; d > 0; d >>= 1) ss += __shfl_down_sync(0xffffffffu, ss, d);
        if ((tid & 31) == 0) atomicAdd(&ssq[b * C_ + c], ss);
    }
}

// ---------------- fused positional branch: dw(pe1) -> gelu -> dw(pe2) + hx ---
__global__ __launch_bounds__(256) void pe_fused(const float* __restrict__ pe1,
                                                const float* __restrict__ pe2,
                                                const float* __restrict__ hx) {
    __shared__ float sv[20][128];
    __shared__ float si[18][128];
    int b = blockIdx.z, c = blockIdx.y, r0 = blockIdx.x * 16;
    const float* Xc = g_v + ((size_t)(b * C_ + c)) * HW_;
    int tid = threadIdx.x;
    for (int i = tid; i < 20 * 32; i += 256) {
        int row = i >> 5, c4 = i & 31;
        int gr = r0 - 2 + row;
        float4 v = make_float4(0.f, 0.f, 0.f, 0.f);
        if (gr >= 0 && gr < H_) v = *reinterpret_cast<const float4*>(Xc + (size_t)gr * W_ + c4 * 4);
        *reinterpret_cast<float4*>(&sv[row][c4 * 4]) = v;
    }
    float wk1[9], wk2[9];
#pragma unroll
    for (int t = 0; t < 9; t++) {
        wk1[t] = __ldg(pe1 + (size_t)c * 9 + t);
        wk2[t] = __ldg(pe2 + (size_t)c * 9 + t);
    }
    __syncthreads();
    // intermediate rows r0-1 .. r0+16 (zero outside image; gelu inside)
    for (int i = tid; i < 18 * 128; i += 256) {
        int ir = i >> 7, col = i & 127;
        int gri = r0 - 1 + ir;
        float s = 0.f;
        if (gri >= 0 && gri < H_) {
#pragma unroll
            for (int dr = 0; dr < 3; dr++) {
                const float* Sr = sv[ir + dr];
                float l = (col > 0) ? Sr[col - 1] : 0.f;
                float m = Sr[col];
                float r = (col < 127) ? Sr[col + 1] : 0.f;
                s += wk1[dr * 3 + 0] * l + wk1[dr * 3 + 1] * m + wk1[dr * 3 + 2] * r;
            }
            float x3 = s * s * s;
            s = 0.5f * s * (1.f + tanhf(0.7978845608028654f * (s + 0.044715f * x3)));
        }
        si[ir][col] = s;
    }
    __syncthreads();
    float* D = g_bufB + ((size_t)(b * C_ + c)) * HW_;
    const float* Hc = hx + ((size_t)(b * C_ + c)) * HW_;
#pragma unroll
    for (int t = 0; t < 8; t++) {
        int o = tid + t * 256;
        int row = o >> 7, col = o & 127;
        float s = 0.f;
#pragma unroll
        for (int dr = 0; dr < 3; dr++) {
            const float* Sr = si[row + dr];
            float l = (col > 0) ? Sr[col - 1] : 0.f;
            float m = Sr[col];
            float r = (col < 127) ? Sr[col + 1] : 0.f;
            s += wk2[dr * 3 + 0] * l + wk2[dr * 3 + 1] * m + wk2[dr * 3 + 2] * r;
        }
        D[(size_t)(r0 + row) * W_ + col] = s + Hc[(size_t)(r0 + row) * W_ + col];
    }
}

// ---------------- gram via tf32 mma: 32x32 per (b,h), split-K=4 --------------
__global__ __launch_bounds__(256) void gram_mma() {
    __shared__ float sbuf[2 * 32 * 132];   // sq | sk ; reused as reduction buffer
    float* sq = sbuf;
    float* sk = sbuf + 32 * 132;
    int seg = blockIdx.x, h = blockIdx.y, b = blockIdx.z;
    const float* Q = g_q + ((size_t)(b * C_ + h * HD_)) * HW_;
    const float* K = g_k + ((size_t)(b * C_ + h * HD_)) * HW_;
    int tid = threadIdx.x, wid = tid >> 5, lane = tid & 31;
    int g = lane >> 2, tig = lane & 3;
    float acc[2][4][4] = {};
    int n0 = seg * (HW_ / GSEG);
    for (int ch = 0; ch < (HW_ / GSEG) / 128; ch++) {
        int base = n0 + ch * 128;
        for (int i = tid; i < 32 * 32; i += 256) {
            int row = i >> 5, c4 = i & 31;
            *reinterpret_cast<float4*>(&sq[row * 132 + c4 * 4]) =
                *reinterpret_cast<const float4*>(Q + (size_t)row * HW_ + base + c4 * 4);
            *reinterpret_cast<float4*>(&sk[row * 132 + c4 * 4]) =
                *reinterpret_cast<const float4*>(K + (size_t)row * HW_ + base + c4 * 4);
        }
        __syncthreads();
        int kl0 = wid * 16;
#pragma unroll
        for (int s = 0; s < 2; s++) {
            int kl = kl0 + s * 8;
            unsigned afr[2][4];
#pragma unroll
            for (int mt = 0; mt < 2; mt++) {
                int r = mt * 16 + g;
                afr[mt][0] = __float_as_uint(sq[r * 132 + kl + tig]);
                afr[mt][1] = __float_as_uint(sq[(r + 8) * 132 + kl + tig]);
                afr[mt][2] = __float_as_uint(sq[r * 132 + kl + tig + 4]);
                afr[mt][3] = __float_as_uint(sq[(r + 8) * 132 + kl + tig + 4]);
            }
#pragma unroll
            for (int nt = 0; nt < 4; nt++) {
                unsigned b0 = __float_as_uint(sk[(nt * 8 + g) * 132 + kl + tig]);
                unsigned b1 = __float_as_uint(sk[(nt * 8 + g) * 132 + kl + tig + 4]);
#pragma unroll
                for (int mt = 0; mt < 2; mt++)
                    mma_tf32(acc[mt][nt], afr[mt], b0, b1);
            }
        }
        __syncthreads();
    }
    // cross-warp reduce via smem
    float* red = sbuf;
#pragma unroll
    for (int mt = 0; mt < 2; mt++)
#pragma unroll
        for (int nt = 0; nt < 4; nt++) {
            int r = mt * 16 + g, cl = nt * 8 + 2 * tig;
            red[wid * 1024 + r * 32 + cl] = acc[mt][nt][0];
            red[wid * 1024 + r * 32 + cl + 1] = acc[mt][nt][1];
            red[wid * 1024 + (r + 8) * 32 + cl] = acc[mt][nt][2];
            red[wid * 1024 + (r + 8) * 32 + cl + 1] = acc[mt][nt][3];
        }
    __syncthreads();
    float* outp = g_part + ((size_t)(b * HEADS_ + h) * GSEG + seg) * 1024;
    for (int i = tid; i < 1024; i += 256) {
        float s = 0.f;
#pragma unroll
        for (int w = 0; w < 8; w++) s += red[w * 1024 + i];
        outp[i] = s;
    }
}

// ---------------- softmax with fused q/k norm scales + temperature -----------
__global__ void softmax_kernel(const float* __restrict__ temp) {
    int bh = blockIdx.x;
    int b = bh >> 3, h = bh & 7;
    int i = threadIdx.x;
    float qs = 1.f / fmaxf(sqrtf(g_ss[b * C_ + h * HD_ + i]), 1e-12f);
    float T = __ldg(temp + h);
    float v[32];
    float mx = -1e30f;
#pragma unroll 4
    for (int j = 0; j < 32; j++) {
        float s = 0.f;
#pragma unroll
        for (int seg = 0; seg < GSEG; seg++)
            s += g_part[((size_t)bh * GSEG + seg) * 1024 + i * 32 + j];
        float ks = 1.f / fmaxf(sqrtf(g_ss[B_ * C_ + b * C_ + h * HD_ + j]), 1e-12f);
        float val = s * qs * ks * T;
        v[j] = val;
        mx = fmaxf(mx, val);
    }
    float sum = 0.f;
#pragma unroll
    for (int j = 0; j < 32; j++) {
        v[j] = expf(v[j] - mx);
        sum += v[j];
    }
    float inv = 1.f / sum;
#pragma unroll
    for (int j = 0; j < 32; j++) g_attn[bh * 1024 + i * 32 + j] = v[j] * inv;
}

// ---------------- M[b] = ao_w @ blockdiag(attn[b]) ---------------------------
__global__ void buildM_kernel(const float* __restrict__ ao_w) {
    int h = blockIdx.x, b = blockIdx.y;
    int tid = threadIdx.x;
    __shared__ float sa[32][33];
#pragma unroll
    for (int t = 0; t < 4; t++) {
        int idx = tid + t * 256;
        sa[idx >> 5][idx & 31] = g_attn[(b * HEADS_ + h) * 1024 + idx];
    }
    __syncthreads();
    float wreg[32];
#pragma unroll
    for (int c = 0; c < 32; c++) wreg[c] = ao_w[(size_t)tid * C_ + h * HD_ + c];
#pragma unroll 4
    for (int d = 0; d < 32; d++) {
        float m = 0.f;
#pragma unroll
        for (int c = 0; c < 32; c++) m += wreg[c] * sa[c][d];
        g_M[((size_t)(b * C_) + tid) * C_ + h * HD_ + d] = m;
    }
}

// -----------------------------------------------------------------------------
extern "C" void kernel_launch(void* const* d_in, const int* in_sizes, int n_in,
                              void* d_out, int out_size) {
    const float* x = (const float*)d_in[0];
    const float* hx = (const float*)d_in[1];
    const float* ln1_w = (const float*)d_in[2];
    const float* ln1_b = (const float*)d_in[3];
    const float* ln2_w = (const float*)d_in[4];
    const float* ln2_b = (const float*)d_in[5];
    const float* q_w = (const float*)d_in[6];
    const float* q_b = (const float*)d_in[7];
    const float* q_dw_w = (const float*)d_in[8];
    const float* q_dw_b = (const float*)d_in[9];
    const float* kv_w = (const float*)d_in[10];
    const float* kv_b = (const float*)d_in[11];
    const float* kv_dw_w = (const float*)d_in[12];
    const float* kv_dw_b = (const float*)d_in[13];
    const float* ao_w = (const float*)d_in[14];
    const float* ao_b = (const float*)d_in[15];
    const float* pe1_w = (const float*)d_in[16];
    const float* pe2_w = (const float*)d_in[17];
    const float* temperature = (const float*)d_in[18];
    float* out = (float*)d_out;

    float *p_Wq, *p_Wkv, *p_bq, *p_bkv, *p_rsq, *p_rskv;
    float *p_bufA, *p_bufB, *p_q, *p_k, *p_v, *p_M, *p_ss;
    cudaGetSymbolAddress((void**)&p_Wq, g_Wq);
    cudaGetSymbolAddress((void**)&p_Wkv, g_Wkv);
    cudaGetSymbolAddress((void**)&p_bq, g_bq);
    cudaGetSymbolAddress((void**)&p_bkv, g_bkv);
    cudaGetSymbolAddress((void**)&p_rsq, g_rsq);
    cudaGetSymbolAddress((void**)&p_rskv, g_rskv);
    cudaGetSymbolAddress((void**)&p_bufA, g_bufA);
    cudaGetSymbolAddress((void**)&p_bufB, g_bufB);
    cudaGetSymbolAddress((void**)&p_q, g_q);
    cudaGetSymbolAddress((void**)&p_k, g_k);
    cudaGetSymbolAddress((void**)&p_v, g_v);
    cudaGetSymbolAddress((void**)&p_M, g_M);
    cudaGetSymbolAddress((void**)&p_ss, g_ss);

    const int gemm_smem = 2 * ST_FLOATS * 4;   // 71680 bytes
    cudaFuncSetAttribute(gemm_tc_kernel, cudaFuncAttributeMaxDynamicSharedMemorySize, gemm_smem);

    // 1. fold LN into weights; zero sumsq accumulators
    prep_w_kernel<<<3 * C_, 256>>>(q_w, q_b, ln1_w, ln1_b, kv_w, kv_b, ln2_w, ln2_b);

    // 2. q_pre = conv1x1(ln(x)); kv_pre = conv1x1(ln(hx))   (stats in-kernel)
    {
        GemmArgs ga{};
        ga.X = x; ga.Wg = p_Wq; ga.bias = p_bq; ga.rsum = p_rsq;
        ga.Y = p_bufA; ga.O = C_; ga.mode = 0; ga.perBatchW = 0;
        gemm_tc_kernel<<<dim3(HW_ / 128, C_ / 128, B_), 256, gemm_smem>>>(ga);
    }
    {
        GemmArgs ga{};
        ga.X = hx; ga.Wg = p_Wkv; ga.bias = p_bkv; ga.rsum = p_rskv;
        ga.Y = p_bufB; ga.O = 2 * C_; ga.mode = 0; ga.perBatchW = 0;
        gemm_tc_kernel<<<dim3(HW_ / 128, 2 * C_ / 128, B_), 256, gemm_smem>>>(ga);
    }

    // 3. depthwise convs (tiled), fused sumsq for q and k
    dw_tiled<<<dim3(8, C_, B_), 256>>>(p_bufA, q_dw_w, q_dw_b, p_q, p_q, C_, C_, p_ss);
    dw_tiled<<<dim3(8, 2 * C_, B_), 256>>>(p_bufB, kv_dw_w, kv_dw_b, p_k, p_v, C_, 2 * C_,
                                           p_ss + B_ * C_);

    // 4. fused positional branch -> bufB (= p_emb + hx)
    pe_fused<<<dim3(8, C_, B_), 256>>>(pe1_w, pe2_w, hx);

    // 5. gram (tf32 mma, split-K=4), softmax with fused norms
    gram_mma<<<dim3(GSEG, HEADS_, B_), 256>>>();
    softmax_kernel<<<B_ * HEADS_, 32>>>(temperature);

    // 6. fold attn into output projection; final fused GEMM
    buildM_kernel<<<dim3(HEADS_, B_), 256>>>(ao_w);
    {
        GemmArgs ga{};
        ga.X = p_v; ga.Wg = p_M; ga.bias = ao_b; ga.pemb = p_bufB;
        ga.Y = out; ga.O = C_; ga.mode = 1; ga.perBatchW = 1;
        gemm_tc_kernel<<<dim3(HW_ / 128, C_ / 128, B_), 256, gemm_smem>>>(ga);
    }
}